// round 14
// baseline (speedup 1.0000x reference)
#include <cuda_runtime.h>
#include <cuda_bf16.h>
#include <stdint.h>

#define S_LEN 1024
#define HD    64
#define BM    64             // Q rows per CTA (4 warps x 16 rows)
#define BN    128            // KV rows per tile
#define QTILES (S_LEN / BM)  // 16
#define KT    (S_LEN / BN)   // 8
#define NB    128

// ---------------- device scratch (no cudaMalloc allowed) ----------------
#define KV_U4 ((size_t)NB * S_LEN * HD / 8)
__device__ uint4 g_khi[KV_U4];
__device__ uint4 g_klo[KV_U4];
__device__ uint4 g_vhi[KV_U4];
__device__ uint4 g_vlo[KV_U4];

// ---------------- helpers ----------------
__device__ __forceinline__ uint32_t smem_u32(const void* p) {
    uint32_t a;
    asm("{ .reg .u64 t; cvta.to.shared.u64 t, %1; cvt.u32.u64 %0, t; }"
        : "=r"(a) : "l"(p));
    return a;
}

__device__ __forceinline__ void split2(float a, float b, uint32_t& h, uint32_t& l) {
    __nv_bfloat162 H = __floats2bfloat162_rn(a, b);
    float ra = a - __bfloat162float(H.x);
    float rb = b - __bfloat162float(H.y);
    __nv_bfloat162 L = __floats2bfloat162_rn(ra, rb);
    h = *(uint32_t*)&H;
    l = *(uint32_t*)&L;
}

__device__ __forceinline__ float ex2f(float x) {
    float y;
    asm("ex2.approx.f32 %0, %1;" : "=f"(y) : "f"(x));
    return y;
}

#define LDSM4(r0, r1, r2, r3, addr) \
    asm volatile("ldmatrix.sync.aligned.m8n8.x4.shared.b16 {%0,%1,%2,%3}, [%4];" \
                 : "=r"(r0), "=r"(r1), "=r"(r2), "=r"(r3) : "r"(addr))

#define LDSM4T(r0, r1, r2, r3, addr) \
    asm volatile("ldmatrix.sync.aligned.m8n8.x4.trans.shared.b16 {%0,%1,%2,%3}, [%4];" \
                 : "=r"(r0), "=r"(r1), "=r"(r2), "=r"(r3) : "r"(addr))

#define MMA16816(c, a0, a1, a2, a3, b0, b1) \
    asm volatile("mma.sync.aligned.m16n8k16.row.col.f32.bf16.bf16.f32 " \
                 "{%0,%1,%2,%3}, {%4,%5,%6,%7}, {%8,%9}, {%0,%1,%2,%3};" \
                 : "+f"((c)[0]), "+f"((c)[1]), "+f"((c)[2]), "+f"((c)[3]) \
                 : "r"(a0), "r"(a1), "r"(a2), "r"(a3), "r"(b0), "r"(b1))

#define CP16(sm, gp)  asm volatile("cp.async.cg.shared.global [%0], [%1], 16;" :: "r"(sm), "l"(gp))
#define CP_COMMIT()   asm volatile("cp.async.commit_group;" ::: "memory")
#define CP_WAIT(n)    asm volatile("cp.async.wait_group %0;" :: "n"(n) : "memory")

// ---------------- pre-kernel: bf16 hi/lo split of K and V ----------------
__global__ __launch_bounds__(256)
void presplit_kernel(const float* __restrict__ k, const float* __restrict__ v) {
    const float4* k4 = (const float4*)k;
    const float4* v4 = (const float4*)v;
    uint2* kh = (uint2*)g_khi;
    uint2* kl = (uint2*)g_klo;
    uint2* vh = (uint2*)g_vhi;
    uint2* vl = (uint2*)g_vlo;
    const size_t n4 = (size_t)NB * S_LEN * HD / 4;
    for (size_t i = (size_t)blockIdx.x * 256 + threadIdx.x; i < n4;
         i += (size_t)gridDim.x * 256) {
        float4 x = k4[i];
        uint2 H, L;
        split2(x.x, x.y, H.x, L.x);
        split2(x.z, x.w, H.y, L.y);
        kh[i] = H; kl[i] = L;
        x = v4[i];
        split2(x.x, x.y, H.x, L.x);
        split2(x.z, x.w, H.y, L.y);
        vh[i] = H; vl[i] = L;
    }
}

// ---------------- main kernel ----------------
// smem: four bf16 tiles [128 rows][72 elems] (64 data + 8 pad), 144 B/row.
#define TILEB  (128 * 144)      // 18432 bytes
#define KH_OFF 0
#define KL_OFF (1 * TILEB)
#define VH_OFF (2 * TILEB)
#define VL_OFF (3 * TILEB)
#define SMEM_TOTAL (4 * TILEB)  // 73728 bytes -> 3 CTAs/SM (216 KB)

__device__ __forceinline__ void issue_pair(uint32_t dh, uint32_t dl,
                                           const uint4* gh, const uint4* gl, int tid) {
    #pragma unroll
    for (int i = 0; i < 8; i++) {
        int f = tid + i * 128;
        uint32_t off = (uint32_t)(f >> 3) * 144 + (f & 7) * 16;
        CP16(dh + off, gh + f);
        CP16(dl + off, gl + f);
    }
}

__global__ __launch_bounds__(128, 3)
void mea_mma_kernel(const float* __restrict__ q, float* __restrict__ out) {
    extern __shared__ char sc[];
    const uint32_t sb = smem_u32(sc);
    const int tid  = threadIdx.x;
    const int lane = tid & 31;
    const int w    = tid >> 5;            // warp 0..3 -> Q rows 16w..16w+15
    const int gid  = lane >> 2;
    const int tig  = lane & 3;
    const int b    = blockIdx.x / QTILES;
    const int qi   = blockIdx.x % QTILES;
    const int q0   = qi * BM;

    // ---- stage Q (64x64 fp32, scaled by log2e, -> bf16 hi/lo) via K buffer ----
    {
        const float L2E = 1.4426950408889634f;
        const float4* qg4 = (const float4*)(q + ((size_t)b * S_LEN + q0) * HD);
        #pragma unroll
        for (int i = 0; i < 4; i++) {
            int f8 = tid + i * 128;
            float4 x = qg4[2 * f8], y = qg4[2 * f8 + 1];
            uint4 H, L;
            split2(x.x * L2E, x.y * L2E, H.x, L.x);
            split2(x.z * L2E, x.w * L2E, H.y, L.y);
            split2(y.x * L2E, y.y * L2E, H.z, L.z);
            split2(y.z * L2E, y.w * L2E, H.w, L.w);
            uint32_t off = (uint32_t)(f8 >> 3) * 144 + (f8 & 7) * 16;
            *(uint4*)(sc + KH_OFF + off) = H;
            *(uint4*)(sc + KL_OFF + off) = L;
        }
    }
    __syncthreads();

    // ---- hoist Q A-fragments into registers ----
    uint32_t qh[4][4], ql[4][4];
    {
        const uint32_t aQ = sb + KH_OFF
            + (uint32_t)(w * 16 + (lane & 15)) * 144 + ((lane >> 4) & 1) * 16;
        #pragma unroll
        for (int kc = 0; kc < 4; kc++) {
            LDSM4(qh[kc][0], qh[kc][1], qh[kc][2], qh[kc][3], aQ + kc * 32);
            LDSM4(ql[kc][0], ql[kc][1], ql[kc][2], ql[kc][3], aQ + TILEB + kc * 32);
        }
    }
    __syncthreads();    // Q staging fully read before K(0) overwrites it

    const uint4* khB = g_khi + (size_t)b * S_LEN * 8;
    const uint4* klB = g_klo + (size_t)b * S_LEN * 8;
    const uint4* vhB = g_vhi + (size_t)b * S_LEN * 8;
    const uint4* vlB = g_vlo + (size_t)b * S_LEN * 8;

    // prefetch tile 0
    issue_pair(sb + KH_OFF, sb + KL_OFF, khB, klB, tid);
    CP_COMMIT();
    issue_pair(sb + VH_OFF, sb + VL_OFF, vhB, vlB, tid);
    CP_COMMIT();

    const uint32_t bK = sb + KH_OFF
        + (uint32_t)((lane & 7) + ((lane >> 4) & 1) * 8) * 144
        + ((lane >> 3) & 1) * 16;
    const uint32_t bV = sb + VH_OFF
        + (uint32_t)((lane & 7) + ((lane >> 3) & 1) * 8) * 144
        + ((lane >> 4) & 1) * 16;

    float o[8][4];
    #pragma unroll
    for (int g = 0; g < 8; g++)
        #pragma unroll
        for (int j = 0; j < 4; j++) o[g][j] = 0.0f;
    float rsum0 = 0.0f, rsum1 = 0.0f;

    #pragma unroll 1
    for (int t = 0; t < KT; t++) {
        const int tn = (t + 1) & (KT - 1);

        CP_WAIT(1);          // K(t) ready (V(t) may still be in flight)
        __syncthreads();

        // ---- S = Q K^T, 3xBF16 (B-fragment temps in groups of 2 np) ----
        float s[16][4];
        #pragma unroll
        for (int g = 0; g < 16; g++)
            #pragma unroll
            for (int j = 0; j < 4; j++) s[g][j] = 0.0f;

        #pragma unroll
        for (int kc = 0; kc < 4; kc++) {
            #pragma unroll
            for (int g2 = 0; g2 < 4; g2++) {          // np pairs {0,1}..{6,7}
                uint32_t bh[2][4], bl[2][4];
                #pragma unroll
                for (int j = 0; j < 2; j++) {
                    const int np = g2 * 2 + j;
                    LDSM4(bh[j][0], bh[j][1], bh[j][2], bh[j][3],
                          bK + np * 2304 + kc * 32);
                    LDSM4(bl[j][0], bl[j][1], bl[j][2], bl[j][3],
                          bK + TILEB + np * 2304 + kc * 32);
                }
                #pragma unroll
                for (int j = 0; j < 2; j++) {
                    const int np = g2 * 2 + j;
                    MMA16816(s[2*np],   qh[kc][0], qh[kc][1], qh[kc][2], qh[kc][3], bh[j][0], bh[j][1]);
                    MMA16816(s[2*np+1], qh[kc][0], qh[kc][1], qh[kc][2], qh[kc][3], bh[j][2], bh[j][3]);
                    MMA16816(s[2*np],   qh[kc][0], qh[kc][1], qh[kc][2], qh[kc][3], bl[j][0], bl[j][1]);
                    MMA16816(s[2*np+1], qh[kc][0], qh[kc][1], qh[kc][2], qh[kc][3], bl[j][2], bl[j][3]);
                    MMA16816(s[2*np],   ql[kc][0], ql[kc][1], ql[kc][2], ql[kc][3], bh[j][0], bh[j][1]);
                    MMA16816(s[2*np+1], ql[kc][0], ql[kc][1], ql[kc][2], ql[kc][3], bh[j][2], bh[j][3]);
                }
            }
        }

        __syncthreads();     // all warps done reading K tile
        issue_pair(sb + KH_OFF, sb + KL_OFF, khB + (size_t)tn * 1024,
                   klB + (size_t)tn * 1024, tid);
        CP_COMMIT();

        // ---- exp + row sums + split for ALL blocks (kills s before PV) ----
        uint32_t ph[8][4], pl[8][4];
        #pragma unroll
        for (int kc = 0; kc < 8; kc++) {
            float a0 = ex2f(s[2*kc][0]),   a1 = ex2f(s[2*kc][1]);
            float a2 = ex2f(s[2*kc][2]),   a3 = ex2f(s[2*kc][3]);
            float b0 = ex2f(s[2*kc+1][0]), b1 = ex2f(s[2*kc+1][1]);
            float b2 = ex2f(s[2*kc+1][2]), b3 = ex2f(s[2*kc+1][3]);
            rsum0 += a0 + a1 + b0 + b1;
            rsum1 += a2 + a3 + b2 + b3;
            split2(a0, a1, ph[kc][0], pl[kc][0]);
            split2(a2, a3, ph[kc][1], pl[kc][1]);
            split2(b0, b1, ph[kc][2], pl[kc][2]);
            split2(b2, b3, ph[kc][3], pl[kc][3]);
        }

        CP_WAIT(1);          // V(t) ready (K(t+1) may still be in flight)
        __syncthreads();

        // ---- O += P V, 3xBF16 (V-fragment temps in groups of 2 np) ----
        #pragma unroll
        for (int kc = 0; kc < 8; kc++) {
            #pragma unroll
            for (int g2 = 0; g2 < 2; g2++) {          // np pairs {0,1},{2,3}
                uint32_t vh[2][4], vl[2][4];
                #pragma unroll
                for (int j = 0; j < 2; j++) {
                    const int np = g2 * 2 + j;
                    LDSM4T(vh[j][0], vh[j][1], vh[j][2], vh[j][3],
                           bV + kc * 2304 + np * 32);
                    LDSM4T(vl[j][0], vl[j][1], vl[j][2], vl[j][3],
                           bV + TILEB + kc * 2304 + np * 32);
                }
                #pragma unroll
                for (int j = 0; j < 2; j++) {
                    const int np = g2 * 2 + j;
                    MMA16816(o[2*np],   ph[kc][0], ph[kc][1], ph[kc][2], ph[kc][3], vh[j][0], vh[j][1]);
                    MMA16816(o[2*np+1], ph[kc][0], ph[kc][1], ph[kc][2], ph[kc][3], vh[j][2], vh[j][3]);
                    MMA16816(o[2*np],   ph[kc][0], ph[kc][1], ph[kc][2], ph[kc][3], vl[j][0], vl[j][1]);
                    MMA16816(o[2*np+1], ph[kc][0], ph[kc][1], ph[kc][2], ph[kc][3], vl[j][2], vl[j][3]);
                    MMA16816(o[2*np],   pl[kc][0], pl[kc][1], pl[kc][2], pl[kc][3], vh[j][0], vh[j][1]);
                    MMA16816(o[2*np+1], pl[kc][0], pl[kc][1], pl[kc][2], pl[kc][3], vh[j][2], vh[j][3]);
                }
            }
        }

        __syncthreads();     // all warps done reading V tile
        issue_pair(sb + VH_OFF, sb + VL_OFF, vhB + (size_t)tn * 1024,
                   vlB + (size_t)tn * 1024, tid);
        CP_COMMIT();
    }

    CP_WAIT(0);   // drain trailing prefetches before CTA exit

    // ---- epilogue: quad-reduce row sums, normalize, store ----
    rsum0 += __shfl_xor_sync(0xffffffffu, rsum0, 1);
    rsum0 += __shfl_xor_sync(0xffffffffu, rsum0, 2);
    rsum1 += __shfl_xor_sync(0xffffffffu, rsum1, 1);
    rsum1 += __shfl_xor_sync(0xffffffffu, rsum1, 2);
    const float inv0 = 1.0f / rsum0;
    const float inv1 = 1.0f / rsum1;

    float* orow = out + ((size_t)b * S_LEN + q0 + w * 16 + gid) * HD;
    #pragma unroll
    for (int g = 0; g < 8; g++) {
        float2 lo = make_float2(o[g][0] * inv0, o[g][1] * inv0);
        float2 hi = make_float2(o[g][2] * inv1, o[g][3] * inv1);
        *(float2*)(orow + 8 * g + 2 * tig)          = lo;
        *(float2*)(orow + 8 * HD + 8 * g + 2 * tig) = hi;
    }
}

// ---------------- launch ----------------
extern "C" void kernel_launch(void* const* d_in, const int* in_sizes, int n_in,
                              void* d_out, int out_size)
{
    const float* q = (const float*)d_in[0];
    const float* k = (const float*)d_in[1];
    const float* v = (const float*)d_in[2];
    float* out = (float*)d_out;

    const int nb = in_sizes[0] / (S_LEN * HD);   // 128

    cudaFuncSetAttribute(mea_mma_kernel,
                         cudaFuncAttributeMaxDynamicSharedMemorySize, SMEM_TOTAL);

    presplit_kernel<<<2048, 256>>>(k, v);
    mea_mma_kernel<<<nb * QTILES, 128, SMEM_TOTAL>>>(q, out);
}

// round 15
// speedup vs baseline: 1.1648x; 1.1648x over previous
#include <cuda_runtime.h>
#include <cuda_bf16.h>
#include <stdint.h>

#define S_LEN 1024
#define HD    64
#define BM    128            // Q rows per CTA (4 warps x 32 rows)
#define BN    64             // KV rows per tile
#define QTILES (S_LEN / BM)  // 8
#define KTILES (S_LEN / BN)  // 16
#define NB    128

// ---------------- device scratch (no cudaMalloc allowed) ----------------
#define KV_U4 ((size_t)NB * S_LEN * HD / 8)
__device__ uint4 g_khi[KV_U4];
__device__ uint4 g_klo[KV_U4];
__device__ uint4 g_vhi[KV_U4];
__device__ uint4 g_vlo[KV_U4];

// ---------------- helpers ----------------
__device__ __forceinline__ uint32_t smem_u32(const void* p) {
    uint32_t a;
    asm("{ .reg .u64 t; cvta.to.shared.u64 t, %1; cvt.u32.u64 %0, t; }"
        : "=r"(a) : "l"(p));
    return a;
}

__device__ __forceinline__ void split2(float a, float b, uint32_t& h, uint32_t& l) {
    __nv_bfloat162 H = __floats2bfloat162_rn(a, b);
    float ra = a - __bfloat162float(H.x);
    float rb = b - __bfloat162float(H.y);
    __nv_bfloat162 L = __floats2bfloat162_rn(ra, rb);
    h = *(uint32_t*)&H;
    l = *(uint32_t*)&L;
}

__device__ __forceinline__ float ex2f(float x) {
    float y;
    asm("ex2.approx.f32 %0, %1;" : "=f"(y) : "f"(x));
    return y;
}

#define LDSM4(r0, r1, r2, r3, addr) \
    asm volatile("ldmatrix.sync.aligned.m8n8.x4.shared.b16 {%0,%1,%2,%3}, [%4];" \
                 : "=r"(r0), "=r"(r1), "=r"(r2), "=r"(r3) : "r"(addr))

#define LDSM4T(r0, r1, r2, r3, addr) \
    asm volatile("ldmatrix.sync.aligned.m8n8.x4.trans.shared.b16 {%0,%1,%2,%3}, [%4];" \
                 : "=r"(r0), "=r"(r1), "=r"(r2), "=r"(r3) : "r"(addr))

#define MMA16816(c, a, b0, b1) \
    asm volatile("mma.sync.aligned.m16n8k16.row.col.f32.bf16.bf16.f32 " \
                 "{%0,%1,%2,%3}, {%4,%5,%6,%7}, {%8,%9}, {%0,%1,%2,%3};" \
                 : "+f"((c)[0]), "+f"((c)[1]), "+f"((c)[2]), "+f"((c)[3]) \
                 : "r"((a)[0]), "r"((a)[1]), "r"((a)[2]), "r"((a)[3]), \
                   "r"(b0), "r"(b1))

#define CP16(sm, gp)  asm volatile("cp.async.cg.shared.global [%0], [%1], 16;" :: "r"(sm), "l"(gp))
#define CP_COMMIT()   asm volatile("cp.async.commit_group;" ::: "memory")
#define CP_WAIT(n)    asm volatile("cp.async.wait_group %0;" :: "n"(n) : "memory")

// ---------------- pre-kernel: bf16 hi/lo split of K and V ----------------
__global__ __launch_bounds__(256)
void presplit_kernel(const float* __restrict__ k, const float* __restrict__ v) {
    const float4* k4 = (const float4*)k;
    const float4* v4 = (const float4*)v;
    uint2* kh = (uint2*)g_khi;
    uint2* kl = (uint2*)g_klo;
    uint2* vh = (uint2*)g_vhi;
    uint2* vl = (uint2*)g_vlo;
    const size_t n4 = (size_t)NB * S_LEN * HD / 4;
    for (size_t i = (size_t)blockIdx.x * 256 + threadIdx.x; i < n4;
         i += (size_t)gridDim.x * 256) {
        float4 x = k4[i];
        uint2 H, L;
        split2(x.x, x.y, H.x, L.x);
        split2(x.z, x.w, H.y, L.y);
        kh[i] = H; kl[i] = L;
        x = v4[i];
        split2(x.x, x.y, H.x, L.x);
        split2(x.z, x.w, H.y, L.y);
        vh[i] = H; vl[i] = L;
    }
}

// ---------------- main kernel ----------------
// smem: double-buffered KV tile set. Each buffer: KH,KL,VH,VL of
// [64 rows][72 bf16] (64 data + 8 pad), 144 B/row -> 9216 B per component.
#define COMPB 9216
#define BUFB  (4 * COMPB)        // 36864
#define KH2 0
#define KL2 (1 * COMPB)
#define VH2 (2 * COMPB)
#define VL2 (3 * COMPB)
#define SMEM_TOTAL (2 * BUFB)    // 73728 -> 2 CTAs/SM

// stage one 64-row KV tile (4 components) via cp.async: 16 x 16B per thread
__device__ __forceinline__ void issue_tile(uint32_t sbuf,
                                           const uint4* kh, const uint4* kl,
                                           const uint4* vh, const uint4* vl, int tid) {
    #pragma unroll
    for (int i = 0; i < 4; i++) {
        int f = tid + i * 128;                       // 0..511 = row*8 + colgroup
        uint32_t off = (uint32_t)(f >> 3) * 144 + (f & 7) * 16;
        CP16(sbuf + KH2 + off, kh + f);
        CP16(sbuf + KL2 + off, kl + f);
        CP16(sbuf + VH2 + off, vh + f);
        CP16(sbuf + VL2 + off, vl + f);
    }
}

__global__ __launch_bounds__(128, 2)
void mea_mma_kernel(const float* __restrict__ q, float* __restrict__ out) {
    extern __shared__ char sc[];
    const uint32_t sb = smem_u32(sc);
    const int tid  = threadIdx.x;
    const int lane = tid & 31;
    const int w    = tid >> 5;            // warp 0..3 -> Q rows 32w..32w+31
    const int gid  = lane >> 2;
    const int tig  = lane & 3;
    const int b    = blockIdx.x / QTILES;
    const int qi   = blockIdx.x % QTILES;
    const int q0   = qi * BM;

    // ---- stage+split Q (128x64 fp32, scaled by log2e) in two 64-row passes,
    //      through buffer 0's KH/KL areas; hoist A-fragments to registers ----
    uint32_t qh[2][4][4], ql[2][4][4];    // [m16 group][kc][frag]
    {
        const float L2E = 1.4426950408889634f;
        #pragma unroll 1
        for (int p = 0; p < 2; p++) {
            const float4* qg4 =
                (const float4*)(q + ((size_t)b * S_LEN + q0 + p * 64) * HD);
            #pragma unroll
            for (int i = 0; i < 4; i++) {
                int f8 = tid + i * 128;           // row*8 + colgroup, row < 64
                float4 x = qg4[2 * f8], y = qg4[2 * f8 + 1];
                uint4 H, L;
                split2(x.x * L2E, x.y * L2E, H.x, L.x);
                split2(x.z * L2E, x.w * L2E, H.y, L.y);
                split2(y.x * L2E, y.y * L2E, H.z, L.z);
                split2(y.z * L2E, y.w * L2E, H.w, L.w);
                uint32_t off = (uint32_t)(f8 >> 3) * 144 + (f8 & 7) * 16;
                *(uint4*)(sc + KH2 + off) = H;
                *(uint4*)(sc + KL2 + off) = L;
            }
            __syncthreads();
            if ((w >> 1) == p) {                   // warps whose rows are staged
                const uint32_t aQ = sb + KH2
                    + (uint32_t)((w & 1) * 32 + (lane & 15)) * 144
                    + ((lane >> 4) & 1) * 16;
                #pragma unroll
                for (int g = 0; g < 2; g++)
                    #pragma unroll
                    for (int kc = 0; kc < 4; kc++) {
                        LDSM4(qh[g][kc][0], qh[g][kc][1], qh[g][kc][2], qh[g][kc][3],
                              aQ + g * 16 * 144 + kc * 32);
                        LDSM4(ql[g][kc][0], ql[g][kc][1], ql[g][kc][2], ql[g][kc][3],
                              aQ + COMPB + g * 16 * 144 + kc * 32);
                    }
            }
            __syncthreads();                       // staging read before reuse
        }
    }

    const uint4* khB = g_khi + (size_t)b * S_LEN * 8;
    const uint4* klB = g_klo + (size_t)b * S_LEN * 8;
    const uint4* vhB = g_vhi + (size_t)b * S_LEN * 8;
    const uint4* vlB = g_vlo + (size_t)b * S_LEN * 8;

    // prefetch tiles 0 and 1 into the two buffers
    issue_tile(sb,        khB,       klB,       vhB,       vlB,       tid);
    CP_COMMIT();
    issue_tile(sb + BUFB, khB + 512, klB + 512, vhB + 512, vlB + 512, tid);
    CP_COMMIT();

    float o[2][8][4];
    #pragma unroll
    for (int g = 0; g < 2; g++)
        #pragma unroll
        for (int d = 0; d < 8; d++)
            #pragma unroll
            for (int j = 0; j < 4; j++) o[g][d][j] = 0.0f;
    float rs[2][2] = {{0.0f, 0.0f}, {0.0f, 0.0f}};

    #pragma unroll 1
    for (int t = 0; t < KTILES; t++) {
        const uint32_t bufo = (uint32_t)(t & 1) * BUFB;

        CP_WAIT(1);          // tile t's cp.async group complete
        __syncthreads();     // ...and visible to all threads

        const uint32_t bK = sb + bufo + KH2
            + (uint32_t)((lane & 7) + ((lane >> 4) & 1) * 8) * 144
            + ((lane >> 3) & 1) * 16;
        const uint32_t bV = sb + bufo + VH2
            + (uint32_t)((lane & 7) + ((lane >> 3) & 1) * 8) * 144
            + ((lane >> 4) & 1) * 16;

        // ---- S = Q K^T, 3xBF16; each B fragment feeds both m16 groups ----
        float s[2][8][4];
        #pragma unroll
        for (int g = 0; g < 2; g++)
            #pragma unroll
            for (int np = 0; np < 8; np++)
                #pragma unroll
                for (int j = 0; j < 4; j++) s[g][np][j] = 0.0f;

        #pragma unroll
        for (int kc = 0; kc < 4; kc++)
            #pragma unroll
            for (int grp = 0; grp < 4; grp++) {   // 16-key groups
                uint32_t bh[4], bl[4];
                LDSM4(bh[0], bh[1], bh[2], bh[3], bK + grp * 2304 + kc * 32);
                LDSM4(bl[0], bl[1], bl[2], bl[3], bK + COMPB + grp * 2304 + kc * 32);
                #pragma unroll
                for (int g = 0; g < 2; g++) {
                    MMA16816(s[g][2*grp],   qh[g][kc], bh[0], bh[1]);
                    MMA16816(s[g][2*grp+1], qh[g][kc], bh[2], bh[3]);
                    MMA16816(s[g][2*grp],   qh[g][kc], bl[0], bl[1]);
                    MMA16816(s[g][2*grp+1], qh[g][kc], bl[2], bl[3]);
                    MMA16816(s[g][2*grp],   ql[g][kc], bh[0], bh[1]);
                    MMA16816(s[g][2*grp+1], ql[g][kc], bh[2], bh[3]);
                }
            }

        // ---- exp (Q pre-scaled -> ex2) + row sums + split (s dies here) ----
        uint32_t ph[2][4][4], pl[2][4][4];
        #pragma unroll
        for (int g = 0; g < 2; g++)
            #pragma unroll
            for (int kc = 0; kc < 4; kc++) {
                float a0 = ex2f(s[g][2*kc][0]),   a1 = ex2f(s[g][2*kc][1]);
                float a2 = ex2f(s[g][2*kc][2]),   a3 = ex2f(s[g][2*kc][3]);
                float b0 = ex2f(s[g][2*kc+1][0]), b1 = ex2f(s[g][2*kc+1][1]);
                float b2 = ex2f(s[g][2*kc+1][2]), b3 = ex2f(s[g][2*kc+1][3]);
                rs[g][0] += a0 + a1 + b0 + b1;
                rs[g][1] += a2 + a3 + b2 + b3;
                split2(a0, a1, ph[g][kc][0], pl[g][kc][0]);
                split2(a2, a3, ph[g][kc][1], pl[g][kc][1]);
                split2(b0, b1, ph[g][kc][2], pl[g][kc][2]);
                split2(b2, b3, ph[g][kc][3], pl[g][kc][3]);
            }

        // ---- O += P V, 3xBF16; each V fragment feeds both m16 groups ----
        #pragma unroll
        for (int kc = 0; kc < 4; kc++)
            #pragma unroll
            for (int np = 0; np < 4; np++) {      // d16 groups
                uint32_t vh[4], vl[4];
                LDSM4T(vh[0], vh[1], vh[2], vh[3], bV + kc * 2304 + np * 32);
                LDSM4T(vl[0], vl[1], vl[2], vl[3], bV + COMPB + kc * 2304 + np * 32);
                #pragma unroll
                for (int g = 0; g < 2; g++) {
                    MMA16816(o[g][2*np],   ph[g][kc], vh[0], vh[1]);
                    MMA16816(o[g][2*np+1], ph[g][kc], vh[2], vh[3]);
                    MMA16816(o[g][2*np],   ph[g][kc], vl[0], vl[1]);
                    MMA16816(o[g][2*np+1], ph[g][kc], vl[2], vl[3]);
                    MMA16816(o[g][2*np],   pl[g][kc], vh[0], vh[1]);
                    MMA16816(o[g][2*np+1], pl[g][kc], vh[2], vh[3]);
                }
            }

        __syncthreads();     // all warps done reading this buffer
        const int tn = (t + 2) & (KTILES - 1);
        issue_tile(sb + bufo, khB + (size_t)tn * 512, klB + (size_t)tn * 512,
                   vhB + (size_t)tn * 512, vlB + (size_t)tn * 512, tid);
        CP_COMMIT();
    }

    CP_WAIT(0);   // drain trailing (wrapped) prefetches before CTA exit

    // ---- epilogue: quad-reduce 4 row sums, normalize, store ----
    #pragma unroll
    for (int g = 0; g < 2; g++)
        #pragma unroll
        for (int j = 0; j < 2; j++) {
            rs[g][j] += __shfl_xor_sync(0xffffffffu, rs[g][j], 1);
            rs[g][j] += __shfl_xor_sync(0xffffffffu, rs[g][j], 2);
        }

    #pragma unroll
    for (int g = 0; g < 2; g++) {
        const float i0 = 1.0f / rs[g][0];
        const float i1 = 1.0f / rs[g][1];
        float* orow = out + ((size_t)b * S_LEN + q0 + w * 32 + g * 16 + gid) * HD;
        #pragma unroll
        for (int d = 0; d < 8; d++) {
            *(float2*)(orow + d * 8 + 2 * tig) =
                make_float2(o[g][d][0] * i0, o[g][d][1] * i0);
            *(float2*)(orow + 8 * HD + d * 8 + 2 * tig) =
                make_float2(o[g][d][2] * i1, o[g][d][3] * i1);
        }
    }
}

// ---------------- launch ----------------
extern "C" void kernel_launch(void* const* d_in, const int* in_sizes, int n_in,
                              void* d_out, int out_size)
{
    const float* q = (const float*)d_in[0];
    const float* k = (const float*)d_in[1];
    const float* v = (const float*)d_in[2];
    float* out = (float*)d_out;

    const int nb = in_sizes[0] / (S_LEN * HD);   // 128

    cudaFuncSetAttribute(mea_mma_kernel,
                         cudaFuncAttributeMaxDynamicSharedMemorySize, SMEM_TOTAL);

    presplit_kernel<<<2048, 256>>>(k, v);
    mea_mma_kernel<<<nb * QTILES, 128, SMEM_TOTAL>>>(q, out);
}